// round 15
// baseline (speedup 1.0000x reference)
#include <cuda_runtime.h>
#include <cuda_fp16.h>
#include <cstdint>

// ---------------------------------------------------------------------------
// BodyTransformer via single-pass fp16 mma.sync GEMMs + cp.async (sm_103)
// R14 + 3 CTAs/SM (6 warps/SMSP) to cover LDSM latency.
// ---------------------------------------------------------------------------

#define MM 131072

__device__ __align__(16) __half g_h[(size_t)MM * 256];        // LN output
__device__ __align__(16) float  g_qkv[(size_t)MM * 768];
__device__ __align__(16) __half g_o[(size_t)MM * 256];        // attn output
__device__ __align__(16) __half g_u[(size_t)MM * 1024];       // ffn1 output
__device__ __align__(16) __half g_Bqkv[768 * 256];
__device__ __align__(16) __half g_Bo[256 * 256];
__device__ __align__(16) __half g_B1[1024 * 256];
__device__ __align__(16) __half g_B2[256 * 1024];

static __device__ __forceinline__ uint32_t smem_u32(const void* p) {
    uint32_t a;
    asm("{ .reg .u64 t; cvta.to.shared.u64 t, %1; cvt.u32.u64 %0, t; }"
        : "=r"(a) : "l"(p));
    return a;
}
static __device__ __forceinline__ void ldm4(uint32_t* r, uint32_t addr) {
    asm volatile("ldmatrix.sync.aligned.m8n8.x4.shared.b16 {%0,%1,%2,%3}, [%4];"
                 : "=r"(r[0]), "=r"(r[1]), "=r"(r[2]), "=r"(r[3]) : "r"(addr));
}
static __device__ __forceinline__ void mma_fp16(float* d, const uint32_t* a,
                                                uint32_t b0, uint32_t b1) {
    asm volatile(
        "mma.sync.aligned.m16n8k16.row.col.f32.f16.f16.f32 "
        "{%0,%1,%2,%3}, {%4,%5,%6,%7}, {%8,%9}, {%0,%1,%2,%3};"
        : "+f"(d[0]), "+f"(d[1]), "+f"(d[2]), "+f"(d[3])
        : "r"(a[0]), "r"(a[1]), "r"(a[2]), "r"(a[3]), "r"(b0), "r"(b1));
}
static __device__ __forceinline__ void cpasync16(uint32_t sa, const void* g) {
    asm volatile("cp.async.cg.shared.global [%0], [%1], 16;"
                 :: "r"(sa), "l"(g) : "memory");
}
static __device__ __forceinline__ void cp_commit() {
    asm volatile("cp.async.commit_group;" ::: "memory");
}
static __device__ __forceinline__ void cp_wait1() {
    asm volatile("cp.async.wait_group 1;" ::: "memory");
}
static __device__ __forceinline__ uint32_t pack_h2(float x, float y) {
    __half2 h = __floats2half2_rn(x, y);
    return *(uint32_t*)&h;
}

// ---------------------------------------------------------------------------
// Pipelined GEMM: D[128x128] = A[m0..,K] * B[n0..,K]^T (+ epilogue)
// 2-stage cp.async, K-chunk 64. Row stride 72 fp16 (144 B) — granule
// (9r+c)%8 distinct over 8 rows -> conflict-free ldmatrix.
// Stage: A@0 (18432 B) | B@18432 (18432 B); 2 stages = 73728 B -> 3 CTA/SM.
// MODE 0: fp32 +bias [qkv]; 1: relu+bias -> fp16 [ffn1]; 2: resid += [wo,ffn2]
// ---------------------------------------------------------------------------
#define RW 72
#define ARRB 18432
#define STGB (2 * ARRB)

template <int MODE>
static __device__ __forceinline__ void gemm_body(
    const __half* __restrict__ A, const __half* __restrict__ B,
    const float* __restrict__ bias, float* __restrict__ outF,
    __half* __restrict__ outH, float* __restrict__ resid,
    int K, int out_ld) {
    extern __shared__ __half sm[];

    const int tid = threadIdx.x;
    const int wid = tid >> 5;
    const int lane = tid & 31;
    const int wm = wid >> 2;       // 0..1 (64 rows)
    const int wn = wid & 3;        // 0..3 (32 cols)
    const int n0 = blockIdx.x * 128;
    const int m0 = blockIdx.y * 128;

    const __half* __restrict__ gA = A + (size_t)m0 * K;
    const __half* __restrict__ gB = B + (size_t)n0 * K;
    const uint32_t smBase = smem_u32(sm);

    float acc[4][4][4];
#pragma unroll
    for (int mt = 0; mt < 4; ++mt)
#pragma unroll
        for (int nt = 0; nt < 4; ++nt)
#pragma unroll
            for (int e = 0; e < 4; ++e) acc[mt][nt][e] = 0.f;

    const int nst = K >> 6;

    auto load_stage = [&](int s) {
        const uint32_t sb = smBase + (uint32_t)((s & 1) * STGB);
        const int kc = s * 64;
#pragma unroll
        for (int i = 0; i < 8; ++i) {
            const int idx = tid + i * 256;       // 0..2047
            const int a2 = idx >> 10;            // 0=A, 1=B
            const int r = (idx >> 3) & 127;
            const int c = idx & 7;
            const uint32_t sa = sb + (uint32_t)(a2 * ARRB + r * 144 + c * 16);
            const __half* g = (a2 == 0 ? gA : gB);
            cpasync16(sa, g + (size_t)r * K + kc + c * 8);
        }
        cp_commit();
    };

    load_stage(0);
    if (nst > 1) load_stage(1); else cp_commit();

    const uint32_t aOff = (uint32_t)((wm * 64 + (lane & 15)) * 144 + ((lane >> 4) << 4));
    const uint32_t bOff = (uint32_t)((wn * 32 + (lane & 15)) * 144 + ((lane >> 4) << 4));

    for (int s = 0; s < nst; ++s) {
        cp_wait1();
        __syncthreads();
        const uint32_t sb = smBase + (uint32_t)((s & 1) * STGB);
        const uint32_t aB = sb + aOff;
        const uint32_t bB = sb + ARRB + bOff;
#pragma unroll
        for (int st = 0; st < 4; ++st) {                 // 4 x k16
            const uint32_t koff = (uint32_t)(st * 32);   // 16 fp16 = 32 B
            uint32_t bfr[2][4];
            ldm4(bfr[0], bB + koff);
            ldm4(bfr[1], bB + koff + 16 * 144);
            uint32_t afr[4][4];
            ldm4(afr[0], aB + koff);
            ldm4(afr[1], aB + koff + 16 * 144);
            ldm4(afr[2], aB + koff + 32 * 144);
            ldm4(afr[3], aB + koff + 48 * 144);
            // 16 independent accumulators per k16 step
#pragma unroll
            for (int mt = 0; mt < 4; ++mt)
#pragma unroll
                for (int nt = 0; nt < 4; ++nt) {
                    const int np = nt >> 1, sel = nt & 1;
                    mma_fp16(acc[mt][nt], afr[mt],
                             bfr[np][sel], bfr[np][sel + 2]);
                }
        }
        __syncthreads();
        if (s + 2 < nst) load_stage(s + 2);
        else cp_commit();
    }

    const int r0 = lane >> 2;
    const int c0 = (lane & 3) * 2;
#pragma unroll
    for (int mt = 0; mt < 4; ++mt) {
#pragma unroll
        for (int nt = 0; nt < 4; ++nt) {
            const int gc = n0 + wn * 32 + nt * 8 + c0;
            const float bx = bias[gc], by = bias[gc + 1];
#pragma unroll
            for (int half = 0; half < 2; ++half) {
                const int gr = m0 + wm * 64 + mt * 16 + r0 + half * 8;
                float vx = acc[mt][nt][2 * half] + bx;
                float vy = acc[mt][nt][2 * half + 1] + by;
                const size_t ro = (size_t)gr * out_ld + gc;
                if (MODE == 0) {
                    *(float2*)(outF + ro) = make_float2(vx, vy);
                } else if (MODE == 2) {
                    float2 xv = *(float2*)(resid + ro);
                    xv.x += vx; xv.y += vy;
                    *(float2*)(resid + ro) = xv;
                } else {
                    vx = fmaxf(vx, 0.f); vy = fmaxf(vy, 0.f);
                    *(uint32_t*)(outH + ro) = pack_h2(vx, vy);
                }
            }
        }
    }
}

__global__ void __launch_bounds__(256, 3)
k_gemm_qkv(const float* __restrict__ bias) {
    gemm_body<0>(g_h, g_Bqkv, bias, g_qkv, nullptr, nullptr, 256, 768);
}
__global__ void __launch_bounds__(256, 3)
k_gemm_wo(const float* __restrict__ bias, float* __restrict__ x) {
    gemm_body<2>(g_o, g_Bo, bias, nullptr, nullptr, x, 256, 256);
}
__global__ void __launch_bounds__(256, 3)
k_gemm_ffn1(const float* __restrict__ bias) {
    gemm_body<1>(g_h, g_B1, bias, nullptr, g_u, nullptr, 256, 1024);
}
__global__ void __launch_bounds__(256, 3)
k_gemm_ffn2(const float* __restrict__ bias, float* __restrict__ x) {
    gemm_body<2>(g_u, g_B2, bias, nullptr, nullptr, x, 1024, 256);
}

// ---------------- LayerNorm: x -> fp16 ---------------------------------------
__global__ void __launch_bounds__(256)
k_ln(const float* __restrict__ x, const float* __restrict__ g,
     const float* __restrict__ bta) {
    const int row = blockIdx.x * 8 + (threadIdx.x >> 5);
    const int lane = threadIdx.x & 31;
    const float* rp = x + (size_t)row * 256 + lane * 8;
    const float4 a = *(const float4*)rp;
    const float4 b4 = *(const float4*)(rp + 4);
    float vals[8] = {a.x, a.y, a.z, a.w, b4.x, b4.y, b4.z, b4.w};
    float s = 0.f, s2 = 0.f;
#pragma unroll
    for (int j = 0; j < 8; ++j) { s += vals[j]; s2 = fmaf(vals[j], vals[j], s2); }
#pragma unroll
    for (int off = 16; off; off >>= 1) {
        s += __shfl_xor_sync(0xffffffffu, s, off);
        s2 += __shfl_xor_sync(0xffffffffu, s2, off);
    }
    const float mean = s * 0.00390625f;
    const float var = s2 * 0.00390625f - mean * mean;
    const float rstd = rsqrtf(var + 1e-5f);
    uint32_t ph[4];
#pragma unroll
    for (int j = 0; j < 4; ++j) {
        const int c0 = lane * 8 + 2 * j;
        float v0 = (vals[2 * j] - mean) * rstd * g[c0] + bta[c0];
        float v1 = (vals[2 * j + 1] - mean) * rstd * g[c0 + 1] + bta[c0 + 1];
        ph[j] = pack_h2(v0, v1);
    }
    const size_t o = (size_t)row * 256 + lane * 8;
    *(uint4*)(g_h + o) = make_uint4(ph[0], ph[1], ph[2], ph[3]);
}

// ---------------- Attention (fp32, banded |i-j|<=1) --------------------------
__global__ void __launch_bounds__(256, 2)
k_attn() {
    extern __shared__ float smf[];  // [32][776]
    const int b = blockIdx.x;
    const int tid = threadIdx.x;
    const int wid = tid >> 5;
    const int lane = tid & 31;
    const float* gq = g_qkv + (size_t)b * 24576;
    for (int r = wid; r < 32; r += 8)
#pragma unroll
        for (int j = 0; j < 24; ++j)
            smf[r * 776 + j * 32 + lane] = gq[r * 768 + j * 32 + lane];
    __syncthreads();

    const int h = wid;
    float kreg[32];
#pragma unroll
    for (int d = 0; d < 32; ++d)
        kreg[d] = smf[lane * 776 + 256 + h * 32 + d];
    const float SC = 0.17677669529663689f;
    for (int i = 0; i < 32; ++i) {
        const float* qrow = smf + i * 776 + h * 32;
        float s = 0.f;
#pragma unroll
        for (int d = 0; d < 32; ++d) s = fmaf(qrow[d], kreg[d], s);
        s *= SC;
        int dj = lane - i;
        if (dj < 0) dj = -dj;
        if (dj > 1) s -= 1e9f;
        float m = s;
#pragma unroll
        for (int off = 16; off; off >>= 1)
            m = fmaxf(m, __shfl_xor_sync(0xffffffffu, m, off));
        const float e = expf(s - m);
        float sum = e;
#pragma unroll
        for (int off = 16; off; off >>= 1)
            sum += __shfl_xor_sync(0xffffffffu, sum, off);
        const float w = e / sum;
        float o = 0.f;
        const int j0 = (i > 0) ? i - 1 : 0;
        const int j1 = (i < 31) ? i + 1 : 31;
        for (int j = j0; j <= j1; ++j) {
            const float wj = __shfl_sync(0xffffffffu, w, j);
            o = fmaf(wj, smf[j * 776 + 512 + h * 32 + lane], o);
        }
        g_o[(size_t)(b * 32 + i) * 256 + h * 32 + lane] = __float2half_rn(o);
    }
}

// ---------------- merged weight prep ----------------------------------------
__global__ void k_split_all(const float* __restrict__ wqkv,
                            const float* __restrict__ wo,
                            const float* __restrict__ w1,
                            const float* __restrict__ w2) {
    int i = blockIdx.x * 256 + threadIdx.x;
    if (i < 196608) {
        g_Bqkv[i] = __float2half_rn(wqkv[i]);
    } else if (i < 262144) {
        int j = i - 196608;
        g_Bo[j] = __float2half_rn(wo[j]);
    } else if (i < 524288) {
        int j = i - 262144;
        int f = j >> 8, k = j & 255;
        g_B1[j] = __float2half_rn(w1[k * 1024 + f]);
    } else if (i < 786432) {
        int j = i - 524288;
        int c = j >> 10, k = j & 1023;
        g_B2[j] = __float2half_rn(w2[k * 256 + c]);
    }
}

// ---------------- Tokenizer (fp32, proven) -----------------------------------
__global__ void __launch_bounds__(256)
bt_tokenize(const float* __restrict__ obs, const float* __restrict__ embW,
            const float* __restrict__ embB, const float* __restrict__ pos,
            float* __restrict__ out) {
    __shared__ float obs_s[32 * 128];
    const int n = blockIdx.x;
    const int b0 = blockIdx.y * 32;
    const int tid = threadIdx.x;
    const float* src = obs + b0 * 128;
    for (int i = tid; i < 4096; i += 256) obs_s[i] = src[i];
    __syncthreads();
    const int e = tid;
    float acc[32];
#pragma unroll
    for (int bb = 0; bb < 32; ++bb) acc[bb] = 0.f;
    const float* wb = embW + n * 32768 + e;
    for (int d0 = 0; d0 < 128; d0 += 16) {
        float w[16];
#pragma unroll
        for (int dd = 0; dd < 16; ++dd) w[dd] = wb[(d0 + dd) * 256];
#pragma unroll
        for (int bb = 0; bb < 32; ++bb) {
            const float4* orow = (const float4*)(obs_s + bb * 128 + d0);
            float4 o0 = orow[0], o1 = orow[1], o2 = orow[2], o3 = orow[3];
            float a = acc[bb];
            a = fmaf(o0.x, w[0], a);  a = fmaf(o0.y, w[1], a);
            a = fmaf(o0.z, w[2], a);  a = fmaf(o0.w, w[3], a);
            a = fmaf(o1.x, w[4], a);  a = fmaf(o1.y, w[5], a);
            a = fmaf(o1.z, w[6], a);  a = fmaf(o1.w, w[7], a);
            a = fmaf(o2.x, w[8], a);  a = fmaf(o2.y, w[9], a);
            a = fmaf(o2.z, w[10], a); a = fmaf(o2.w, w[11], a);
            a = fmaf(o3.x, w[12], a); a = fmaf(o3.y, w[13], a);
            a = fmaf(o3.z, w[14], a); a = fmaf(o3.w, w[15], a);
            acc[bb] = a;
        }
    }
    const float add = embB[n * 256 + e] + pos[n * 256 + e];
#pragma unroll
    for (int bb = 0; bb < 32; ++bb)
        out[(b0 + bb) * 8192 + n * 256 + e] = acc[bb] + add;
}

extern "C" void kernel_launch(void* const* d_in, const int* in_sizes, int n_in,
                              void* d_out, int out_size) {
    (void)in_sizes; (void)n_in; (void)out_size;
    const float* obs  = (const float*)d_in[0];
    const float* embW = (const float*)d_in[1];
    const float* embB = (const float*)d_in[2];
    const float* pos  = (const float*)d_in[3];
    const float* Wqkv = (const float*)d_in[4];
    const float* bqkv = (const float*)d_in[5];
    const float* Wo   = (const float*)d_in[6];
    const float* bo   = (const float*)d_in[7];
    const float* ln1g = (const float*)d_in[8];
    const float* ln1b = (const float*)d_in[9];
    const float* ln2g = (const float*)d_in[10];
    const float* ln2b = (const float*)d_in[11];
    const float* W1   = (const float*)d_in[12];
    const float* b1   = (const float*)d_in[13];
    const float* W2   = (const float*)d_in[14];
    const float* b2   = (const float*)d_in[15];
    float* x = (float*)d_out;

    const int GSMEM = 2 * STGB;       // 73728 B
    const int ASMEM = 32 * 776 * 4;   // 99328 B
    cudaFuncSetAttribute(k_gemm_qkv,  cudaFuncAttributeMaxDynamicSharedMemorySize, GSMEM);
    cudaFuncSetAttribute(k_gemm_wo,   cudaFuncAttributeMaxDynamicSharedMemorySize, GSMEM);
    cudaFuncSetAttribute(k_gemm_ffn1, cudaFuncAttributeMaxDynamicSharedMemorySize, GSMEM);
    cudaFuncSetAttribute(k_gemm_ffn2, cudaFuncAttributeMaxDynamicSharedMemorySize, GSMEM);
    cudaFuncSetAttribute(k_attn,      cudaFuncAttributeMaxDynamicSharedMemorySize, ASMEM);
    cudaFuncSetAttribute(k_gemm_qkv,  cudaFuncAttributePreferredSharedMemoryCarveout, 100);
    cudaFuncSetAttribute(k_gemm_wo,   cudaFuncAttributePreferredSharedMemoryCarveout, 100);
    cudaFuncSetAttribute(k_gemm_ffn1, cudaFuncAttributePreferredSharedMemoryCarveout, 100);
    cudaFuncSetAttribute(k_gemm_ffn2, cudaFuncAttributePreferredSharedMemoryCarveout, 100);

    k_split_all<<<3072, 256>>>(Wqkv, Wo, W1, W2);
    bt_tokenize<<<dim3(32, 128), 256>>>(obs, embW, embB, pos, x);

    for (int l = 0; l < 6; ++l) {
        k_ln<<<16384, 256>>>(x, ln1g, ln1b);
        k_gemm_qkv<<<dim3(6, 1024), 256, GSMEM>>>(bqkv);
        k_attn<<<4096, 256, ASMEM>>>();
        k_gemm_wo<<<dim3(2, 1024), 256, GSMEM>>>(bo, x);
        k_ln<<<16384, 256>>>(x, ln2g, ln2b);
        k_gemm_ffn1<<<dim3(8, 1024), 256, GSMEM>>>(b1);
        k_gemm_ffn2<<<dim3(2, 1024), 256, GSMEM>>>(b2, x);
    }
}

// round 16
// speedup vs baseline: 1.4151x; 1.4151x over previous
#include <cuda_runtime.h>
#include <cuda_fp16.h>
#include <cstdint>

// ---------------------------------------------------------------------------
// BodyTransformer, fp16 mma.sync GEMMs (sm_103-safe).
// qkv/ffn1: R14 128x128 tiles, (256,2). wo/ffn2: 64x256 tiles with fused
// residual + row-LN epilogue (full E row per CTA), 2 CTAs/SM.
// ---------------------------------------------------------------------------

#define MM 131072

__device__ __align__(16) __half g_h[(size_t)MM * 256];        // LN output
__device__ __align__(16) __half g_qkv[(size_t)MM * 768];
__device__ __align__(16) __half g_o[(size_t)MM * 256];        // attn output
__device__ __align__(16) __half g_u[(size_t)MM * 1024];       // ffn1 output
__device__ __align__(16) __half g_Bqkv[768 * 256];
__device__ __align__(16) __half g_Bo[256 * 256];
__device__ __align__(16) __half g_B1[1024 * 256];
__device__ __align__(16) __half g_B2[256 * 1024];

static __device__ __forceinline__ uint32_t smem_u32(const void* p) {
    uint32_t a;
    asm("{ .reg .u64 t; cvta.to.shared.u64 t, %1; cvt.u32.u64 %0, t; }"
        : "=r"(a) : "l"(p));
    return a;
}
static __device__ __forceinline__ void ldm4(uint32_t* r, uint32_t addr) {
    asm volatile("ldmatrix.sync.aligned.m8n8.x4.shared.b16 {%0,%1,%2,%3}, [%4];"
                 : "=r"(r[0]), "=r"(r[1]), "=r"(r[2]), "=r"(r[3]) : "r"(addr));
}
static __device__ __forceinline__ void mma_fp16(float* d, const uint32_t* a,
                                                uint32_t b0, uint32_t b1) {
    asm volatile(
        "mma.sync.aligned.m16n8k16.row.col.f32.f16.f16.f32 "
        "{%0,%1,%2,%3}, {%4,%5,%6,%7}, {%8,%9}, {%0,%1,%2,%3};"
        : "+f"(d[0]), "+f"(d[1]), "+f"(d[2]), "+f"(d[3])
        : "r"(a[0]), "r"(a[1]), "r"(a[2]), "r"(a[3]), "r"(b0), "r"(b1));
}
static __device__ __forceinline__ void cpasync16(uint32_t sa, const void* g) {
    asm volatile("cp.async.cg.shared.global [%0], [%1], 16;"
                 :: "r"(sa), "l"(g) : "memory");
}
static __device__ __forceinline__ void cp_commit() {
    asm volatile("cp.async.commit_group;" ::: "memory");
}
static __device__ __forceinline__ void cp_wait1() {
    asm volatile("cp.async.wait_group 1;" ::: "memory");
}
static __device__ __forceinline__ uint32_t pack_h2(float x, float y) {
    __half2 h = __floats2half2_rn(x, y);
    return *(uint32_t*)&h;
}

// ===========================================================================
// gemm128 (R14-proven): 128x128 tile, 256 thr, 2-stage K64, row stride 144B.
// MODE 0: fp16 out (+bias) [qkv]; MODE 1: relu(+bias) -> fp16 [ffn1]
// ===========================================================================
#define ARRB 18432
#define STGB (2 * ARRB)

template <int MODE>
static __device__ __forceinline__ void gemm128(
    const __half* __restrict__ A, const __half* __restrict__ B,
    const float* __restrict__ bias, __half* __restrict__ outH,
    int K, int out_ld) {
    extern __shared__ __half sm[];

    const int tid = threadIdx.x;
    const int wid = tid >> 5;
    const int lane = tid & 31;
    const int wm = wid >> 2;
    const int wn = wid & 3;
    const int n0 = blockIdx.x * 128;
    const int m0 = blockIdx.y * 128;

    const __half* __restrict__ gA = A + (size_t)m0 * K;
    const __half* __restrict__ gB = B + (size_t)n0 * K;
    const uint32_t smBase = smem_u32(sm);

    float acc[4][4][4];
#pragma unroll
    for (int mt = 0; mt < 4; ++mt)
#pragma unroll
        for (int nt = 0; nt < 4; ++nt)
#pragma unroll
            for (int e = 0; e < 4; ++e) acc[mt][nt][e] = 0.f;

    const int nst = K >> 6;

    auto load_stage = [&](int s) {
        const uint32_t sb = smBase + (uint32_t)((s & 1) * STGB);
        const int kc = s * 64;
#pragma unroll
        for (int i = 0; i < 8; ++i) {
            const int idx = tid + i * 256;
            const int a2 = idx >> 10;
            const int r = (idx >> 3) & 127;
            const int c = idx & 7;
            const uint32_t sa = sb + (uint32_t)(a2 * ARRB + r * 144 + c * 16);
            const __half* g = (a2 == 0 ? gA : gB);
            cpasync16(sa, g + (size_t)r * K + kc + c * 8);
        }
        cp_commit();
    };

    load_stage(0);
    if (nst > 1) load_stage(1); else cp_commit();

    const uint32_t aOff = (uint32_t)((wm * 64 + (lane & 15)) * 144 + ((lane >> 4) << 4));
    const uint32_t bOff = (uint32_t)((wn * 32 + (lane & 15)) * 144 + ((lane >> 4) << 4));

    for (int s = 0; s < nst; ++s) {
        cp_wait1();
        __syncthreads();
        const uint32_t sb = smBase + (uint32_t)((s & 1) * STGB);
        const uint32_t aB = sb + aOff;
        const uint32_t bB = sb + ARRB + bOff;
#pragma unroll
        for (int st = 0; st < 4; ++st) {
            const uint32_t koff = (uint32_t)(st * 32);
            uint32_t bfr[2][4];
            ldm4(bfr[0], bB + koff);
            ldm4(bfr[1], bB + koff + 16 * 144);
            uint32_t afr[4][4];
            ldm4(afr[0], aB + koff);
            ldm4(afr[1], aB + koff + 16 * 144);
            ldm4(afr[2], aB + koff + 32 * 144);
            ldm4(afr[3], aB + koff + 48 * 144);
#pragma unroll
            for (int mt = 0; mt < 4; ++mt)
#pragma unroll
                for (int nt = 0; nt < 4; ++nt) {
                    const int np = nt >> 1, sel = nt & 1;
                    mma_fp16(acc[mt][nt], afr[mt],
                             bfr[np][sel], bfr[np][sel + 2]);
                }
        }
        __syncthreads();
        if (s + 2 < nst) load_stage(s + 2);
        else cp_commit();
    }

    const int r0 = lane >> 2;
    const int c0 = (lane & 3) * 2;
#pragma unroll
    for (int mt = 0; mt < 4; ++mt)
#pragma unroll
        for (int nt = 0; nt < 4; ++nt) {
            const int gc = n0 + wn * 32 + nt * 8 + c0;
            const float bx = bias[gc], by = bias[gc + 1];
#pragma unroll
            for (int half = 0; half < 2; ++half) {
                const int gr = m0 + wm * 64 + mt * 16 + r0 + half * 8;
                float vx = acc[mt][nt][2 * half] + bx;
                float vy = acc[mt][nt][2 * half + 1] + by;
                if (MODE == 1) { vx = fmaxf(vx, 0.f); vy = fmaxf(vy, 0.f); }
                const size_t ro = (size_t)gr * out_ld + gc;
                *(uint32_t*)(outH + ro) = pack_h2(vx, vy);
            }
        }
}

// ===========================================================================
// gemm64_ln: 64(M) x 256(N) tile, 256 thr, warp tile 32x64, 2-stage K64.
// Epilogue: resid += (+bias) -> x ; fused fp32 row-LN -> g_h (fp16).
// Stage: A@0 (64*144=9216 B) | B@9216 (256*144=36864 B) ; stage=46080 B.
// 2 stages = 92160 B -> 2 CTAs/SM (regs ~110 < 128 cap).
// ===========================================================================
#define A64B 9216
#define STG64 46080

static __device__ __forceinline__ void gemm64_ln(
    const __half* __restrict__ A, const __half* __restrict__ B,
    const float* __restrict__ bias, float* __restrict__ resid,
    const float* __restrict__ lng, const float* __restrict__ lnb,
    __half* __restrict__ outH, int K, int do_ln) {
    extern __shared__ __half sm[];

    const int tid = threadIdx.x;
    const int wid = tid >> 5;
    const int lane = tid & 31;
    const int wm = wid >> 2;       // 0..1 : 32-row group
    const int wn = wid & 3;        // 0..3 : 64-col group
    const int m0 = blockIdx.x * 64;

    const __half* __restrict__ gA = A + (size_t)m0 * K;
    const uint32_t smBase = smem_u32(sm);

    float acc[2][8][4];
#pragma unroll
    for (int mt = 0; mt < 2; ++mt)
#pragma unroll
        for (int nt = 0; nt < 8; ++nt)
#pragma unroll
            for (int e = 0; e < 4; ++e) acc[mt][nt][e] = 0.f;

    const int nst = K >> 6;

    auto load_stage = [&](int s) {
        const uint32_t sb = smBase + (uint32_t)((s & 1) * STG64);
        const int kc = s * 64;
#pragma unroll
        for (int i = 0; i < 10; ++i) {
            const int idx = tid + i * 256;          // 0..2559
            if (idx < 512) {                        // A: 64 rows x 8 c16
                const int r = idx >> 3, c = idx & 7;
                cpasync16(sb + (uint32_t)(r * 144 + c * 16),
                          gA + (size_t)r * K + kc + c * 8);
            } else {                                // B: 256 rows x 8 c16
                const int j = idx - 512;
                const int r = j >> 3, c = j & 7;
                cpasync16(sb + (uint32_t)(A64B + r * 144 + c * 16),
                          B + (size_t)r * K + kc + c * 8);
            }
        }
        cp_commit();
    };

    load_stage(0);
    if (nst > 1) load_stage(1); else cp_commit();

    const uint32_t aOff = (uint32_t)((wm * 32 + (lane & 15)) * 144 + ((lane >> 4) << 4));
    const uint32_t bOff = (uint32_t)((wn * 64 + (lane & 15)) * 144 + ((lane >> 4) << 4));

    for (int s = 0; s < nst; ++s) {
        cp_wait1();
        __syncthreads();
        const uint32_t sb = smBase + (uint32_t)((s & 1) * STG64);
        const uint32_t aB = sb + aOff;
        const uint32_t bB = sb + A64B + bOff;
#pragma unroll
        for (int st = 0; st < 4; ++st) {
            const uint32_t koff = (uint32_t)(st * 32);
            uint32_t bfr[4][4];
            ldm4(bfr[0], bB + koff);
            ldm4(bfr[1], bB + koff + 16 * 144);
            ldm4(bfr[2], bB + koff + 32 * 144);
            ldm4(bfr[3], bB + koff + 48 * 144);
            uint32_t afr[2][4];
            ldm4(afr[0], aB + koff);
            ldm4(afr[1], aB + koff + 16 * 144);
#pragma unroll
            for (int mt = 0; mt < 2; ++mt)
#pragma unroll
                for (int nt = 0; nt < 8; ++nt) {
                    const int np = nt >> 1, sel = nt & 1;
                    mma_fp16(acc[mt][nt], afr[mt],
                             bfr[np][sel], bfr[np][sel + 2]);
                }
        }
        __syncthreads();
        if (s + 2 < nst) load_stage(s + 2);
        else cp_commit();
    }
    __syncthreads();  // smem now reusable for LN reductions

    const int r0 = lane >> 2;
    const int c0 = (lane & 3) * 2;

    float* red_s = (float*)sm;        // [64][4]
    float* red_q = red_s + 256;       // [64][4]
    float* statm = red_q + 256;       // [64]
    float* statr = statm + 64;        // [64]

    float rs[2][2], rq[2][2];
#pragma unroll
    for (int mt = 0; mt < 2; ++mt) { rs[mt][0] = rs[mt][1] = 0.f; rq[mt][0] = rq[mt][1] = 0.f; }

    // residual add + write x + accumulate row stats
#pragma unroll
    for (int mt = 0; mt < 2; ++mt)
#pragma unroll
        for (int nt = 0; nt < 8; ++nt) {
            const int gc = wn * 64 + nt * 8 + c0;
            const float bx = bias[gc], by = bias[gc + 1];
#pragma unroll
            for (int half = 0; half < 2; ++half) {
                const int lr = wm * 32 + mt * 16 + r0 + half * 8;
                const size_t ro = (size_t)(m0 + lr) * 256 + gc;
                float2 xv = *(float2*)(resid + ro);
                float vx = acc[mt][nt][2 * half] + bx + xv.x;
                float vy = acc[mt][nt][2 * half + 1] + by + xv.y;
                *(float2*)(resid + ro) = make_float2(vx, vy);
                acc[mt][nt][2 * half] = vx;
                acc[mt][nt][2 * half + 1] = vy;
                rs[mt][half] += vx + vy;
                rq[mt][half] += vx * vx + vy * vy;
            }
        }

    if (do_ln) {
#pragma unroll
        for (int mt = 0; mt < 2; ++mt)
#pragma unroll
            for (int half = 0; half < 2; ++half) {
                float s = rs[mt][half], q = rq[mt][half];
                s += __shfl_xor_sync(0xffffffffu, s, 1);
                s += __shfl_xor_sync(0xffffffffu, s, 2);
                q += __shfl_xor_sync(0xffffffffu, q, 1);
                q += __shfl_xor_sync(0xffffffffu, q, 2);
                if ((lane & 3) == 0) {
                    const int lr = wm * 32 + mt * 16 + r0 + half * 8;
                    red_s[lr * 4 + wn] = s;
                    red_q[lr * 4 + wn] = q;
                }
            }
        __syncthreads();
        if (tid < 64) {
            float s = 0.f, q = 0.f;
#pragma unroll
            for (int w = 0; w < 4; ++w) { s += red_s[tid * 4 + w]; q += red_q[tid * 4 + w]; }
            const float mean = s * 0.00390625f;
            const float var = q * 0.00390625f - mean * mean;
            statm[tid] = mean;
            statr[tid] = rsqrtf(var + 1e-5f);
        }
        __syncthreads();
#pragma unroll
        for (int mt = 0; mt < 2; ++mt)
#pragma unroll
            for (int nt = 0; nt < 8; ++nt) {
                const int gc = wn * 64 + nt * 8 + c0;
                const float gx = lng[gc], gy = lng[gc + 1];
                const float tx = lnb[gc], ty = lnb[gc + 1];
#pragma unroll
                for (int half = 0; half < 2; ++half) {
                    const int lr = wm * 32 + mt * 16 + r0 + half * 8;
                    const float mean = statm[lr], rstd = statr[lr];
                    const float hx = (acc[mt][nt][2 * half] - mean) * rstd * gx + tx;
                    const float hy = (acc[mt][nt][2 * half + 1] - mean) * rstd * gy + ty;
                    const size_t ro = (size_t)(m0 + lr) * 256 + gc;
                    *(uint32_t*)(outH + ro) = pack_h2(hx, hy);
                }
            }
    }
}

__global__ void __launch_bounds__(256, 2)
k_gemm_qkv(const float* __restrict__ bias) {
    gemm128<0>(g_h, g_Bqkv, bias, g_qkv, 256, 768);
}
__global__ void __launch_bounds__(256, 2)
k_gemm_ffn1(const float* __restrict__ bias) {
    gemm128<1>(g_h, g_B1, bias, g_u, 256, 1024);
}
__global__ void __launch_bounds__(256, 2)
k_gemm_wo_ln(const float* __restrict__ bias, float* __restrict__ x,
             const float* __restrict__ lng, const float* __restrict__ lnb) {
    gemm64_ln(g_o, g_Bo, bias, x, lng, lnb, g_h, 256, 1);
}
__global__ void __launch_bounds__(256, 2)
k_gemm_ffn2_ln(const float* __restrict__ bias, float* __restrict__ x,
               const float* __restrict__ lng, const float* __restrict__ lnb,
               int do_ln) {
    gemm64_ln(g_u, g_B2, bias, x, lng, lnb, g_h, 1024, do_ln);
}

// ---------------- initial LayerNorm: x -> fp16 --------------------------------
__global__ void __launch_bounds__(256)
k_ln(const float* __restrict__ x, const float* __restrict__ g,
     const float* __restrict__ bta) {
    const int row = blockIdx.x * 8 + (threadIdx.x >> 5);
    const int lane = threadIdx.x & 31;
    const float* rp = x + (size_t)row * 256 + lane * 8;
    const float4 a = *(const float4*)rp;
    const float4 b4 = *(const float4*)(rp + 4);
    float vals[8] = {a.x, a.y, a.z, a.w, b4.x, b4.y, b4.z, b4.w};
    float s = 0.f, s2 = 0.f;
#pragma unroll
    for (int j = 0; j < 8; ++j) { s += vals[j]; s2 = fmaf(vals[j], vals[j], s2); }
#pragma unroll
    for (int off = 16; off; off >>= 1) {
        s += __shfl_xor_sync(0xffffffffu, s, off);
        s2 += __shfl_xor_sync(0xffffffffu, s2, off);
    }
    const float mean = s * 0.00390625f;
    const float var = s2 * 0.00390625f - mean * mean;
    const float rstd = rsqrtf(var + 1e-5f);
    uint32_t ph[4];
#pragma unroll
    for (int j = 0; j < 4; ++j) {
        const int c0 = lane * 8 + 2 * j;
        float v0 = (vals[2 * j] - mean) * rstd * g[c0] + bta[c0];
        float v1 = (vals[2 * j + 1] - mean) * rstd * g[c0 + 1] + bta[c0 + 1];
        ph[j] = pack_h2(v0, v1);
    }
    const size_t o = (size_t)row * 256 + lane * 8;
    *(uint4*)(g_h + o) = make_uint4(ph[0], ph[1], ph[2], ph[3]);
}

// ---------------- Attention (fp32 math, fp16 qkv in / fp16 o out) ------------
__global__ void __launch_bounds__(256, 2)
k_attn() {
    extern __shared__ float smf[];  // [32][776]
    const int b = blockIdx.x;
    const int tid = threadIdx.x;
    const int wid = tid >> 5;
    const int lane = tid & 31;
    const __half* gq = g_qkv + (size_t)b * 24576;
    for (int r = wid; r < 32; r += 8)
#pragma unroll
        for (int j = 0; j < 24; ++j)
            smf[r * 776 + j * 32 + lane] =
                __half2float(gq[r * 768 + j * 32 + lane]);
    __syncthreads();

    const int h = wid;
    float kreg[32];
#pragma unroll
    for (int d = 0; d < 32; ++d)
        kreg[d] = smf[lane * 776 + 256 + h * 32 + d];
    const float SC = 0.17677669529663689f;
    for (int i = 0; i < 32; ++i) {
        const float* qrow = smf + i * 776 + h * 32;
        float s = 0.f;
#pragma unroll
        for (int d = 0; d < 32; ++d) s = fmaf(qrow[d], kreg[d], s);
        s *= SC;
        int dj = lane - i;
        if (dj < 0) dj = -dj;
        if (dj > 1) s -= 1e9f;
        float m = s;
#pragma unroll
        for (int off = 16; off; off >>= 1)
            m = fmaxf(m, __shfl_xor_sync(0xffffffffu, m, off));
        const float e = expf(s - m);
        float sum = e;
#pragma unroll
        for (int off = 16; off; off >>= 1)
            sum += __shfl_xor_sync(0xffffffffu, sum, off);
        const float w = e / sum;
        float o = 0.f;
        const int j0 = (i > 0) ? i - 1 : 0;
        const int j1 = (i < 31) ? i + 1 : 31;
        for (int j = j0; j <= j1; ++j) {
            const float wj = __shfl_sync(0xffffffffu, w, j);
            o = fmaf(wj, smf[j * 776 + 512 + h * 32 + lane], o);
        }
        g_o[(size_t)(b * 32 + i) * 256 + h * 32 + lane] = __float2half_rn(o);
    }
}

// ---------------- merged weight prep ----------------------------------------
__global__ void k_split_all(const float* __restrict__ wqkv,
                            const float* __restrict__ wo,
                            const float* __restrict__ w1,
                            const float* __restrict__ w2) {
    int i = blockIdx.x * 256 + threadIdx.x;
    if (i < 196608) {
        g_Bqkv[i] = __float2half_rn(wqkv[i]);
    } else if (i < 262144) {
        int j = i - 196608;
        g_Bo[j] = __float2half_rn(wo[j]);
    } else if (i < 524288) {
        int j = i - 262144;
        int f = j >> 8, k = j & 255;
        g_B1[j] = __float2half_rn(w1[k * 1024 + f]);
    } else if (i < 786432) {
        int j = i - 524288;
        int c = j >> 10, k = j & 1023;
        g_B2[j] = __float2half_rn(w2[k * 256 + c]);
    }
}

// ---------------- Tokenizer (fp32, proven) -----------------------------------
__global__ void __launch_bounds__(256)
bt_tokenize(const float* __restrict__ obs, const float* __restrict__ embW,
            const float* __restrict__ embB, const float* __restrict__ pos,
            float* __restrict__ out) {
    __shared__ float obs_s[32 * 128];
    const int n = blockIdx.x;
    const int b0 = blockIdx.y * 32;
    const int tid = threadIdx.x;
    const float* src = obs + b0 * 128;
    for (int i = tid; i < 4096; i += 256) obs_s[i] = src[i];
    __syncthreads();
    const int e = tid;
    float acc[32];
#pragma unroll
    for (int bb = 0; bb < 32; ++bb) acc[bb] = 0.f;
    const float* wb = embW + n * 32768 + e;
    for (int d0 = 0; d0 < 128; d0 += 16) {
        float w[16];
#pragma unroll
        for (int dd = 0; dd < 16; ++dd) w[dd] = wb[(d0 + dd) * 256];
#pragma unroll
        for (int bb = 0; bb < 32; ++bb) {
            const float4* orow = (const float4*)(obs_s + bb * 128 + d0);
            float4 o0 = orow[0], o1 = orow[1], o2 = orow[2], o3 = orow[3];
            float a = acc[bb];
            a = fmaf(o0.x, w[0], a);  a = fmaf(o0.y, w[1], a);
            a = fmaf(o0.z, w[2], a);  a = fmaf(o0.w, w[3], a);
            a = fmaf(o1.x, w[4], a);  a = fmaf(o1.y, w[5], a);
            a = fmaf(o1.z, w[6], a);  a = fmaf(o1.w, w[7], a);
            a = fmaf(o2.x, w[8], a);  a = fmaf(o2.y, w[9], a);
            a = fmaf(o2.z, w[10], a); a = fmaf(o2.w, w[11], a);
            a = fmaf(o3.x, w[12], a); a = fmaf(o3.y, w[13], a);
            a = fmaf(o3.z, w[14], a); a = fmaf(o3.w, w[15], a);
            acc[bb] = a;
        }
    }
    const float add = embB[n * 256 + e] + pos[n * 256 + e];
#pragma unroll
    for (int bb = 0; bb < 32; ++bb)
        out[(b0 + bb) * 8192 + n * 256 + e] = acc[bb] + add;
}

extern "C" void kernel_launch(void* const* d_in, const int* in_sizes, int n_in,
                              void* d_out, int out_size) {
    (void)in_sizes; (void)n_in; (void)out_size;
    const float* obs  = (const float*)d_in[0];
    const float* embW = (const float*)d_in[1];
    const float* embB = (const float*)d_in[2];
    const float* pos  = (const float*)d_in[3];
    const float* Wqkv = (const float*)d_in[4];
    const float* bqkv = (const float*)d_in[5];
    const float* Wo   = (const float*)d_in[6];
    const float* bo   = (const float*)d_in[7];
    const float* ln1g = (const float*)d_in[8];
    const float* ln1b = (const float*)d_in[9];
    const float* ln2g = (const float*)d_in[10];
    const float* ln2b = (const float*)d_in[11];
    const float* W1   = (const float*)d_in[12];
    const float* b1   = (const float*)d_in[13];
    const float* W2   = (const float*)d_in[14];
    const float* b2   = (const float*)d_in[15];
    float* x = (float*)d_out;

    const int G128 = 2 * STGB;        // 73728 B
    const int G64  = 2 * STG64;       // 92160 B
    const int ASMEM = 32 * 776 * 4;   // 99328 B
    cudaFuncSetAttribute(k_gemm_qkv,     cudaFuncAttributeMaxDynamicSharedMemorySize, G128);
    cudaFuncSetAttribute(k_gemm_ffn1,    cudaFuncAttributeMaxDynamicSharedMemorySize, G128);
    cudaFuncSetAttribute(k_gemm_wo_ln,   cudaFuncAttributeMaxDynamicSharedMemorySize, G64);
    cudaFuncSetAttribute(k_gemm_ffn2_ln, cudaFuncAttributeMaxDynamicSharedMemorySize, G64);
    cudaFuncSetAttribute(k_attn,         cudaFuncAttributeMaxDynamicSharedMemorySize, ASMEM);

    k_split_all<<<3072, 256>>>(Wqkv, Wo, W1, W2);
    bt_tokenize<<<dim3(32, 128), 256>>>(obs, embW, embB, pos, x);
    k_ln<<<16384, 256>>>(x, ln1g, ln1b);

    for (int l = 0; l < 6; ++l) {
        k_gemm_qkv<<<dim3(6, 1024), 256, G128>>>(bqkv);
        k_attn<<<4096, 256, ASMEM>>>();
        k_gemm_wo_ln<<<2048, 256, G64>>>(bo, x, ln2g, ln2b);
        k_gemm_ffn1<<<dim3(8, 1024), 256, G128>>>(b1);
        k_gemm_ffn2_ln<<<2048, 256, G64>>>(b2, x, ln1g, ln1b, (l < 5) ? 1 : 0);
    }
}